// round 15
// baseline (speedup 1.0000x reference)
#include <cuda_runtime.h>
#include <cuda_bf16.h>
#include <cuda_fp16.h>
#include <cstdint>

#define NNODES 10000
#define NEDGES 320000

// ---------------- device scratch (no allocations allowed) ----------------
__device__ int   g_is64;
__device__ int   g_cnt[NNODES];
__device__ int   g_fill[NNODES];
__device__ int   g_rowptr[NNODES + 1];
__device__ float g_dis[NNODES];
__device__ int   g_src[NEDGES];
__device__ float g_norm[NEDGES];
__device__ float g_hw[NNODES * 128];
__device__ float g_t2[NNODES * 64];
__device__ float g_z [NNODES * 64];
__device__ float g_h2[NNODES * 128];
__device__ float g_h3[NNODES * 64];
__device__ float g_az[NNODES * 64];
__device__ float g_ah2[NNODES * 128];
__device__ __align__(16) __nv_bfloat16 g_wt1hi[512 * 128];
__device__ __align__(16) __nv_bfloat16 g_wt1lo[512 * 128];
__device__ __align__(16) __nv_bfloat16 g_wt4hi[128 * 512];
__device__ __align__(16) __nv_bfloat16 g_wt4lo[128 * 512];

__device__ __forceinline__ int load_idx(const void* ei, int pos) {
    if (g_is64) return (int)((const long long*)ei)[pos];
    return ((const int*)ei)[pos];
}

// ---------------- fused zero + dtype detect ----------------
__global__ void init_kernel(const int* __restrict__ ei32) {
    int i = blockIdx.x * blockDim.x + threadIdx.x;
    if (i < NNODES) { g_cnt[i] = 0; g_fill[i] = 0; }
    if (i == 0) {
        int is64 = 1;
        for (int k = 0; k < 128; k++) {
            if (ei32[2 * k + 1] != 0) { is64 = 0; break; }
        }
        g_is64 = is64;
    }
}

__global__ void count_kernel(const void* __restrict__ ei) {
    int e = blockIdx.x * blockDim.x + threadIdx.x;
    if (e < NEDGES) {
        int d = load_idx(ei, NEDGES + e);
        if (d >= 0 && d < NNODES) atomicAdd(&g_cnt[d], 1);
    }
}

// warp-shuffle scan + fused dis = rsqrt(deg+1)
__global__ void scan_kernel() {
    __shared__ int warpsum[32];
    __shared__ int carry;
    int t = threadIdx.x;
    int lane = t & 31, wid = t >> 5;
    if (t == 0) { carry = 0; g_rowptr[0] = 0; }
    __syncthreads();
    for (int base = 0; base < NNODES; base += 1024) {
        int v = (base + t < NNODES) ? g_cnt[base + t] : 0;
        if (base + t < NNODES) g_dis[base + t] = rsqrtf((float)v + 1.0f);
        int x = v;
#pragma unroll
        for (int off = 1; off < 32; off <<= 1) {
            int y = __shfl_up_sync(0xffffffff, x, off);
            if (lane >= off) x += y;
        }
        if (lane == 31) warpsum[wid] = x;
        __syncthreads();
        if (wid == 0) {
            int s = warpsum[lane];
#pragma unroll
            for (int off = 1; off < 32; off <<= 1) {
                int y = __shfl_up_sync(0xffffffff, s, off);
                if (lane >= off) s += y;
            }
            warpsum[lane] = s;
        }
        __syncthreads();
        int incl = x + (wid > 0 ? warpsum[wid - 1] : 0) + carry;
        if (base + t < NNODES) g_rowptr[base + t + 1] = incl;
        __syncthreads();
        if (t == 1023) carry = incl;
        __syncthreads();
    }
}

__global__ void scatter_kernel(const void* __restrict__ ei) {
    int e = blockIdx.x * blockDim.x + threadIdx.x;
    if (e < NEDGES) {
        int srcn = load_idx(ei, e);
        int dstn = load_idx(ei, NEDGES + e);
        if (srcn < 0 || srcn >= NNODES || dstn < 0 || dstn >= NNODES) return;
        int p = g_rowptr[dstn] + atomicAdd(&g_fill[dstn], 1);
        g_src[p]  = srcn;
        g_norm[p] = g_dis[srcn] * g_dis[dstn];
    }
}

// ---------------- weight prep: bf16 split + transpose ----------------
__global__ void wprep_kernel(const float* __restrict__ W,
                             __nv_bfloat16* __restrict__ Whi,
                             __nv_bfloat16* __restrict__ Wlo, int K, int F) {
    int i = blockIdx.x * blockDim.x + threadIdx.x;
    if (i < K * F) {
        int k = i / F, f = i % F;
        float v = W[i];
        __nv_bfloat16 h = __float2bfloat16(v);
        Whi[f * K + k] = h;
        Wlo[f * K + k] = __float2bfloat16(v - __bfloat162float(h));
    }
}

// ---------------- mma.sync helpers ----------------
__device__ __forceinline__ void ldsm_x4(uint32_t* r, uint32_t addr) {
    asm volatile("ldmatrix.sync.aligned.m8n8.x4.shared.b16 {%0,%1,%2,%3}, [%4];"
                 : "=r"(r[0]), "=r"(r[1]), "=r"(r[2]), "=r"(r[3]) : "r"(addr));
}
__device__ __forceinline__ void ldsm_x2(uint32_t* r, uint32_t addr) {
    asm volatile("ldmatrix.sync.aligned.m8n8.x2.shared.b16 {%0,%1}, [%2];"
                 : "=r"(r[0]), "=r"(r[1]) : "r"(addr));
}
__device__ __forceinline__ void mma16816(float* d, const uint32_t* a, const uint32_t* b) {
    asm volatile("mma.sync.aligned.m16n8k16.row.col.f32.bf16.bf16.f32 "
                 "{%0,%1,%2,%3}, {%4,%5,%6,%7}, {%8,%9}, {%0,%1,%2,%3};"
                 : "+f"(d[0]), "+f"(d[1]), "+f"(d[2]), "+f"(d[3])
                 : "r"(a[0]), "r"(a[1]), "r"(a[2]), "r"(a[3]), "r"(b[0]), "r"(b[1]));
}
__device__ __forceinline__ void mma16816h(float* d, const uint32_t* a, const uint32_t* b) {
    asm volatile("mma.sync.aligned.m16n8k16.row.col.f32.f16.f16.f32 "
                 "{%0,%1,%2,%3}, {%4,%5,%6,%7}, {%8,%9}, {%0,%1,%2,%3};"
                 : "+f"(d[0]), "+f"(d[1]), "+f"(d[2]), "+f"(d[3])
                 : "r"(a[0]), "r"(a[1]), "r"(a[2]), "r"(a[3]), "r"(b[0]), "r"(b[1]));
}

__device__ __forceinline__ uint2 split4(float4 v, uint2& lo) {
    __nv_bfloat16 h0 = __float2bfloat16(v.x), h1 = __float2bfloat16(v.y);
    __nv_bfloat16 h2 = __float2bfloat16(v.z), h3 = __float2bfloat16(v.w);
    __nv_bfloat162 hh01 = __halves2bfloat162(h0, h1);
    __nv_bfloat162 hh23 = __halves2bfloat162(h2, h3);
    __nv_bfloat162 ll01 = __halves2bfloat162(
        __float2bfloat16(v.x - __bfloat162float(h0)),
        __float2bfloat16(v.y - __bfloat162float(h1)));
    __nv_bfloat162 ll23 = __halves2bfloat162(
        __float2bfloat16(v.z - __bfloat162float(h2)),
        __float2bfloat16(v.w - __bfloat162float(h3)));
    lo = make_uint2(*(uint32_t*)&ll01, *(uint32_t*)&ll23);
    return make_uint2(*(uint32_t*)&hh01, *(uint32_t*)&hh23);
}

// fp16 conversion of float4 (hi only)
__device__ __forceinline__ uint2 conv4h(float4 v) {
    __half2 hh01 = __halves2half2(__float2half_rn(v.x), __float2half_rn(v.y));
    __half2 hh23 = __halves2half2(__float2half_rn(v.z), __float2half_rn(v.w));
    return make_uint2(*(uint32_t*)&hh01, *(uint32_t*)&hh23);
}

// ---------------- split-bf16 TC GEMM (mma.sync), fp32 A ----------------
#define GP 72
__global__ void mma_gemm_kernel(const float* __restrict__ A,
                                const __nv_bfloat16* __restrict__ Wthi,
                                const __nv_bfloat16* __restrict__ Wtlo,
                                const float* __restrict__ bias,
                                float* __restrict__ C,
                                int M, int K, int F, int dorelu) {
    extern __shared__ __align__(16) char sm[];
    __nv_bfloat16* sAhi = (__nv_bfloat16*)sm;
    __nv_bfloat16* sAlo = sAhi + 128 * GP;
    __nv_bfloat16* sWhi = sAlo + 128 * GP;
    __nv_bfloat16* sWlo = sWhi + 64 * GP;
    int tid = threadIdx.x;
    int bm = blockIdx.y * 128, bf = blockIdx.x * 64;
    int lane = tid & 31, w = tid >> 5;
    int m0 = (w & 3) * 32, n0 = (w >> 2) * 32;
    int ra = lane & 15, ka = (lane >> 4) << 3;
    int rb = lane & 7,  kb = ((lane >> 3) & 1) << 3;
    float acc[2][4][4] = {};

    for (int k0 = 0; k0 < K; k0 += 64) {
        for (int t = tid; t < 128 * 16; t += 256) {
            int r = t >> 4, q = t & 15;
            int gr = bm + r;
            float4 v = make_float4(0.f, 0.f, 0.f, 0.f);
            if (gr < M) v = *(const float4*)(A + (size_t)gr * K + k0 + q * 4);
            uint2 lo, hi = split4(v, lo);
            *(uint2*)(sAhi + r * GP + q * 4) = hi;
            *(uint2*)(sAlo + r * GP + q * 4) = lo;
        }
        for (int t = tid; t < 64 * 8; t += 256) {
            int r = t >> 3, q = t & 7;
            uint4 vh = *(const uint4*)(Wthi + (size_t)(bf + r) * K + k0 + q * 8);
            uint4 vl = *(const uint4*)(Wtlo + (size_t)(bf + r) * K + k0 + q * 8);
            *(uint4*)(sWhi + r * GP + q * 8) = vh;
            *(uint4*)(sWlo + r * GP + q * 8) = vl;
        }
        __syncthreads();
        const __nv_bfloat16* Ats[3] = {sAhi, sAhi, sAlo};
        const __nv_bfloat16* Bts[3] = {sWhi, sWlo, sWhi};
#pragma unroll
        for (int p = 0; p < 3; p++) {
            uint32_t ab = (uint32_t)__cvta_generic_to_shared(Ats[p]);
            uint32_t bb = (uint32_t)__cvta_generic_to_shared(Bts[p]);
#pragma unroll
            for (int ks = 0; ks < 4; ks++) {
                uint32_t a[2][4];
#pragma unroll
                for (int mt = 0; mt < 2; mt++)
                    ldsm_x4(a[mt], ab + (uint32_t)(((m0 + mt * 16 + ra) * GP + ks * 16 + ka) * 2));
                uint32_t b[4][2];
#pragma unroll
                for (int nt = 0; nt < 4; nt++)
                    ldsm_x2(b[nt], bb + (uint32_t)(((n0 + nt * 8 + rb) * GP + ks * 16 + kb) * 2));
#pragma unroll
                for (int mt = 0; mt < 2; mt++)
#pragma unroll
                    for (int nt = 0; nt < 4; nt++)
                        mma16816(acc[mt][nt], a[mt], b[nt]);
            }
        }
        __syncthreads();
    }

#pragma unroll
    for (int mt = 0; mt < 2; mt++)
#pragma unroll
        for (int nt = 0; nt < 4; nt++) {
            int r = bm + m0 + mt * 16 + (lane >> 2);
            int c = bf + n0 + nt * 8 + (lane & 3) * 2;
            float v0 = acc[mt][nt][0], v1 = acc[mt][nt][1];
            float v2 = acc[mt][nt][2], v3 = acc[mt][nt][3];
            if (dorelu) {
                float bb0 = bias[c], bb1 = bias[c + 1];
                v0 = fmaxf(v0 + bb0, 0.0f); v1 = fmaxf(v1 + bb1, 0.0f);
                v2 = fmaxf(v2 + bb0, 0.0f); v3 = fmaxf(v3 + bb1, 0.0f);
            }
            if (r < M)     { C[(size_t)r * F + c] = v0;       C[(size_t)r * F + c + 1] = v1; }
            if (r + 8 < M) { C[(size_t)(r + 8) * F + c] = v2; C[(size_t)(r + 8) * F + c + 1] = v3; }
        }
}

// ---------------- SIMT GEMM (small), fused bias+relu ----------------
__global__ void gemm_kernel(const float* __restrict__ A, const float* __restrict__ B,
                            const float* __restrict__ bias, float* __restrict__ C,
                            int M, int Nn, int K, int dorelu) {
    __shared__ float As[16 * 65];
    __shared__ float Bs[16 * 64];
    int bm = blockIdx.y * 64, bn = blockIdx.x * 64;
    int tid = threadIdx.x;
    int tx = tid & 15, ty = tid >> 4;
    float acc[4][4] = {};
    for (int k0 = 0; k0 < K; k0 += 16) {
        for (int i = tid; i < 1024; i += 256) {
            int r = i >> 4, kk = i & 15;
            int gr = bm + r;
            As[kk * 65 + r] = (gr < M) ? A[(size_t)gr * K + k0 + kk] : 0.0f;
        }
        for (int i = tid; i < 1024; i += 256) {
            int kk = i >> 6, c = i & 63;
            Bs[kk * 64 + c] = B[(k0 + kk) * Nn + bn + c];
        }
        __syncthreads();
#pragma unroll
        for (int kk = 0; kk < 16; kk++) {
            float a[4], b[4];
#pragma unroll
            for (int i = 0; i < 4; i++) a[i] = As[kk * 65 + ty + 16 * i];
#pragma unroll
            for (int j = 0; j < 4; j++) b[j] = Bs[kk * 64 + tx + 16 * j];
#pragma unroll
            for (int i = 0; i < 4; i++)
#pragma unroll
                for (int j = 0; j < 4; j++) acc[i][j] += a[i] * b[j];
        }
        __syncthreads();
    }
#pragma unroll
    for (int i = 0; i < 4; i++) {
        int gr = bm + ty + 16 * i;
        if (gr < M) {
#pragma unroll
            for (int j = 0; j < 4; j++) {
                int gc = bn + tx + 16 * j;
                float v = acc[i][j];
                if (dorelu) v = fmaxf(v + bias[gc], 0.0f);
                C[(size_t)gr * Nn + gc] = v;
            }
        }
    }
}

// ---------------- fused agg(F=128)+bias+relu then @W2 (128->64) ----------------
__global__ void aggw2_kernel(const float* __restrict__ t1, const float* __restrict__ W2,
                             const float* __restrict__ b1, float* __restrict__ t2) {
    __shared__ float W2s[128 * 64];
    __shared__ float h1s[8 * 128];
    __shared__ float b1s[128];
    int tid = threadIdx.x;
    int lane = tid & 31, grp = tid >> 5;
    for (int i = tid; i < 128 * 64; i += 256) W2s[i] = W2[i];
    if (tid < 128) b1s[tid] = b1[tid];
    __syncthreads();

    int n = blockIdx.x * 8 + grp;
    const float4* h4 = (const float4*)t1;
    int f = lane;  // float4 index, F4 = 32
    float4 acc = make_float4(0.f, 0.f, 0.f, 0.f);
    int e = g_rowptr[n], end = g_rowptr[n + 1];
    for (; e + 1 < end; e += 2) {
        int s0 = g_src[e], s1 = g_src[e + 1];
        float w0 = g_norm[e], w1 = g_norm[e + 1];
        float4 v0 = h4[(size_t)s0 * 32 + f];
        float4 v1 = h4[(size_t)s1 * 32 + f];
        acc.x += v0.x * w0 + v1.x * w1;
        acc.y += v0.y * w0 + v1.y * w1;
        acc.z += v0.z * w0 + v1.z * w1;
        acc.w += v0.w * w0 + v1.w * w1;
    }
    if (e < end) {
        int s0 = g_src[e]; float w0 = g_norm[e];
        float4 v0 = h4[(size_t)s0 * 32 + f];
        acc.x += v0.x * w0; acc.y += v0.y * w0; acc.z += v0.z * w0; acc.w += v0.w * w0;
    }
    float d = g_dis[n], dd = d * d;
    float4 sv = h4[(size_t)n * 32 + f];
    float4 bb = ((const float4*)b1s)[f];
    acc.x = fmaxf(acc.x + sv.x * dd + bb.x, 0.f);
    acc.y = fmaxf(acc.y + sv.y * dd + bb.y, 0.f);
    acc.z = fmaxf(acc.z + sv.z * dd + bb.z, 0.f);
    acc.w = fmaxf(acc.w + sv.w * dd + bb.w, 0.f);
    ((float4*)h1s)[grp * 32 + f] = acc;
    __syncthreads();

    float a0 = 0.f, a1 = 0.f;
#pragma unroll 4
    for (int k = 0; k < 128; k++) {
        float a = h1s[grp * 128 + k];
        a0 += a * W2s[k * 64 + lane];
        a1 += a * W2s[k * 64 + lane + 32];
    }
    t2[(size_t)n * 64 + lane]      = a0;
    t2[(size_t)n * 64 + lane + 32] = a1;
}

// ---------------- float4 CSR aggregation (+optional bias/relu) ----------------
__global__ void agg4_kernel(const float* __restrict__ hw, const float* __restrict__ bias,
                            float* __restrict__ out, int F4, int dorelu) {
    int n = blockIdx.x * blockDim.y + threadIdx.y;
    if (n >= NNODES) return;
    int f = threadIdx.x;
    const float4* h4 = (const float4*)hw;
    int e = g_rowptr[n], end = g_rowptr[n + 1];
    float4 acc = make_float4(0.f, 0.f, 0.f, 0.f);
    for (; e + 1 < end; e += 2) {
        int s0 = g_src[e], s1 = g_src[e + 1];
        float w0 = g_norm[e], w1 = g_norm[e + 1];
        float4 v0 = h4[(size_t)s0 * F4 + f];
        float4 v1 = h4[(size_t)s1 * F4 + f];
        acc.x += v0.x * w0 + v1.x * w1;
        acc.y += v0.y * w0 + v1.y * w1;
        acc.z += v0.z * w0 + v1.z * w1;
        acc.w += v0.w * w0 + v1.w * w1;
    }
    if (e < end) {
        int s0 = g_src[e]; float w0 = g_norm[e];
        float4 v0 = h4[(size_t)s0 * F4 + f];
        acc.x += v0.x * w0; acc.y += v0.y * w0; acc.z += v0.z * w0; acc.w += v0.w * w0;
    }
    float d = g_dis[n], dd = d * d;
    float4 sv = h4[(size_t)n * F4 + f];
    acc.x += sv.x * dd; acc.y += sv.y * dd; acc.z += sv.z * dd; acc.w += sv.w * dd;
    if (bias) {
        float4 b = ((const float4*)bias)[f];
        acc.x += b.x; acc.y += b.y; acc.z += b.z; acc.w += b.w;
    }
    if (dorelu) {
        acc.x = fmaxf(acc.x, 0.f); acc.y = fmaxf(acc.y, 0.f);
        acc.z = fmaxf(acc.z, 0.f); acc.w = fmaxf(acc.w, 0.f);
    }
    ((float4*)out)[(size_t)n * F4 + f] = acc;
}

// ---------------- fused agg(F=64) -> az, plus h3 = relu(az@W5+b5) ----------------
// agg part identical layout to agg4 (blockDim 16x16, 16 nodes/block).
// Epilogue: az rows staged in smem; 256 threads compute 16x64 outputs (4/thread).
__global__ void aggw5_kernel(const float* __restrict__ z, const float* __restrict__ W5,
                             const float* __restrict__ b5,
                             float* __restrict__ az, float* __restrict__ h3) {
    __shared__ float W5s[64 * 64];   // 16KB
    __shared__ float azs[16 * 64];   // 4KB
    __shared__ float b5s[64];
    int tid = threadIdx.y * 16 + threadIdx.x;
    for (int i = tid; i < 64 * 64; i += 256) W5s[i] = W5[i];
    if (tid < 64) b5s[tid] = b5[tid];

    int n = blockIdx.x * 16 + threadIdx.y;
    int f = threadIdx.x;
    const float4* h4 = (const float4*)z;
    int e = g_rowptr[n], end = g_rowptr[n + 1];
    float4 acc = make_float4(0.f, 0.f, 0.f, 0.f);
    for (; e + 1 < end; e += 2) {
        int s0 = g_src[e], s1 = g_src[e + 1];
        float w0 = g_norm[e], w1 = g_norm[e + 1];
        float4 v0 = h4[(size_t)s0 * 16 + f];
        float4 v1 = h4[(size_t)s1 * 16 + f];
        acc.x += v0.x * w0 + v1.x * w1;
        acc.y += v0.y * w0 + v1.y * w1;
        acc.z += v0.z * w0 + v1.z * w1;
        acc.w += v0.w * w0 + v1.w * w1;
    }
    if (e < end) {
        int s0 = g_src[e]; float w0 = g_norm[e];
        float4 v0 = h4[(size_t)s0 * 16 + f];
        acc.x += v0.x * w0; acc.y += v0.y * w0; acc.z += v0.z * w0; acc.w += v0.w * w0;
    }
    float d = g_dis[n], dd = d * d;
    float4 sv = h4[(size_t)n * 16 + f];
    acc.x += sv.x * dd; acc.y += sv.y * dd; acc.z += sv.z * dd; acc.w += sv.w * dd;
    ((float4*)az)[(size_t)n * 16 + f] = acc;
    ((float4*)azs)[threadIdx.y * 16 + f] = acc;
    __syncthreads();

    // h3[node yy2, cols c0..c0+3] = relu(sum_k azs[yy2][k]*W5[k][c], + b5)
    int yy2 = tid >> 4;
    int c0 = (tid & 15) * 4;
    float o0 = 0.f, o1 = 0.f, o2 = 0.f, o3 = 0.f;
#pragma unroll 8
    for (int k = 0; k < 64; k++) {
        float a = azs[yy2 * 64 + k];
        o0 += a * W5s[k * 64 + c0];
        o1 += a * W5s[k * 64 + c0 + 1];
        o2 += a * W5s[k * 64 + c0 + 2];
        o3 += a * W5s[k * 64 + c0 + 3];
    }
    int n2 = blockIdx.x * 16 + yy2;
    float4 r;
    r.x = fmaxf(o0 + b5s[c0],     0.f);
    r.y = fmaxf(o1 + b5s[c0 + 1], 0.f);
    r.z = fmaxf(o2 + b5s[c0 + 2], 0.f);
    r.w = fmaxf(o3 + b5s[c0 + 3], 0.f);
    *(float4*)(h3 + (size_t)n2 * 64 + c0) = r;
}

// ---------------- tensor-core a_hat = h3 @ h3^T, fp16 1-pass, triangular grid ----------------
#define AT_PITCH 72

__global__ __launch_bounds__(256) void ahat_mma_kernel(const float* __restrict__ h3,
                                                       float* __restrict__ out) {
    int bid = blockIdx.x;
    int bi = (int)(79.5f - sqrtf(79.5f * 79.5f - 2.0f * (float)bid));
    if (bi < 0) bi = 0;
    if (bi > 78) bi = 78;
#pragma unroll 4
    for (int it = 0; it < 4; it++) {
        int s  = bi * 79 - (bi * (bi - 1)) / 2;
        int s1 = (bi + 1) * 79 - ((bi + 1) * bi) / 2;
        if (bid < s) bi--;
        else if (bid >= s1) bi++;
    }
    int start = bi * 79 - (bi * (bi - 1)) / 2;
    int bj = bi + (bid - start);

    extern __shared__ __align__(16) char sm[];
    __half* Ahi = (__half*)sm;
    __half* Bhi = Ahi + 128 * AT_PITCH;

    int tid = threadIdx.x;

    for (int t = tid; t < 128 * 16; t += 256) {
        int r = t >> 4, q = t & 15;
        int ga = bi * 128 + r;
        float4 v = make_float4(0.f, 0.f, 0.f, 0.f);
        if (ga < NNODES) v = *(const float4*)(h3 + (size_t)ga * 64 + q * 4);
        *(uint2*)(Ahi + r * AT_PITCH + q * 4) = conv4h(v);
        int gb = bj * 128 + r;
        v = make_float4(0.f, 0.f, 0.f, 0.f);
        if (gb < NNODES) v = *(const float4*)(h3 + (size_t)gb * 64 + q * 4);
        *(uint2*)(Bhi + r * AT_PITCH + q * 4) = conv4h(v);
    }
    __syncthreads();

    int lane = tid & 31;
    int w = tid >> 5;
    int m0 = (w & 3) * 32;
    int n0 = (w >> 2) * 64;
    int ra = lane & 15, ka = (lane >> 4) << 3;
    int rb = lane & 7,  kb = ((lane >> 3) & 1) << 3;

    float acc[2][8][4];
#pragma unroll
    for (int mt = 0; mt < 2; mt++)
#pragma unroll
        for (int nt = 0; nt < 8; nt++)
#pragma unroll
            for (int q = 0; q < 4; q++) acc[mt][nt][q] = 0.0f;

    uint32_t abase = (uint32_t)__cvta_generic_to_shared(Ahi);
    uint32_t bbase = (uint32_t)__cvta_generic_to_shared(Bhi);
#pragma unroll
    for (int ks = 0; ks < 4; ks++) {
        uint32_t b[8][2];
#pragma unroll
        for (int nt = 0; nt < 8; nt++)
            ldsm_x2(b[nt], bbase + (uint32_t)(((n0 + nt * 8 + rb) * AT_PITCH + ks * 16 + kb) * 2));
        uint32_t a[2][4];
#pragma unroll
        for (int mt = 0; mt < 2; mt++)
            ldsm_x4(a[mt], abase + (uint32_t)(((m0 + mt * 16 + ra) * AT_PITCH + ks * 16 + ka) * 2));
#pragma unroll
        for (int mt = 0; mt < 2; mt++)
#pragma unroll
            for (int nt = 0; nt < 8; nt++)
                mma16816h(acc[mt][nt], a[mt], b[nt]);
    }
    __syncthreads();

    float* Cs = (float*)sm;  // [128][129]
#pragma unroll
    for (int mt = 0; mt < 2; mt++)
#pragma unroll
        for (int nt = 0; nt < 8; nt++) {
            int row = m0 + mt * 16 + (lane >> 2);
            int col = n0 + nt * 8 + (lane & 3) * 2;
            Cs[row * 129 + col]           = acc[mt][nt][0];
            Cs[row * 129 + col + 1]       = acc[mt][nt][1];
            Cs[(row + 8) * 129 + col]     = acc[mt][nt][2];
            Cs[(row + 8) * 129 + col + 1] = acc[mt][nt][3];
        }
    __syncthreads();

    for (int i = tid; i < 128 * 128; i += 256) {
        int r = i >> 7, c = i & 127;
        int gr = bi * 128 + r, gc = bj * 128 + c;
        if (gr < NNODES && gc < NNODES)
            out[(long long)gr * NNODES + gc] = Cs[r * 129 + c];
    }
    if (bi != bj) {
        for (int i = tid; i < 128 * 128; i += 256) {
            int r = i >> 7, c = i & 127;
            int gr = bj * 128 + r, gc = bi * 128 + c;
            if (gr < NNODES && gc < NNODES)
                out[(long long)gr * NNODES + gc] = Cs[c * 129 + r];
        }
    }
}

// ---------------- host driver ----------------
static void run_gemm(cudaStream_t s, const float* A, const float* B, const float* bias,
                     float* C, int M, int Nn, int K, int dorelu) {
    dim3 grid(Nn / 64, (M + 63) / 64);
    gemm_kernel<<<grid, 256, 0, s>>>(A, B, bias, C, M, Nn, K, dorelu);
}

static void run_agg(cudaStream_t s, const float* hw, const float* b, float* out,
                    int F, int dorelu) {
    int F4 = F / 4;
    int y = 256 / F4;
    dim3 blk(F4, y);
    dim3 grid((NNODES + y - 1) / y);
    agg4_kernel<<<grid, blk, 0, s>>>(hw, b, out, F4, dorelu);
}

extern "C" void kernel_launch(void* const* d_in, const int* in_sizes, int n_in,
                              void* d_out, int out_size) {
    const float* x  = (const float*)d_in[0];
    const void*  ei = d_in[1];
    const float* W1 = (const float*)d_in[2];  const float* b1 = (const float*)d_in[3];
    const float* W2 = (const float*)d_in[4];  const float* b2 = (const float*)d_in[5];
    const float* W3 = (const float*)d_in[6];  const float* b3 = (const float*)d_in[7];
    const float* W4 = (const float*)d_in[8];  const float* b4 = (const float*)d_in[9];
    const float* W5 = (const float*)d_in[10]; const float* b5 = (const float*)d_in[11];

    float* out  = (float*)d_out;
    float* xhat = out;
    float* ahat = out + (size_t)NNODES * 512;

    void* p;
    cudaGetSymbolAddress(&p, g_hw);    float* hw  = (float*)p;
    cudaGetSymbolAddress(&p, g_t2);    float* t2  = (float*)p;
    cudaGetSymbolAddress(&p, g_z);     float* z   = (float*)p;
    cudaGetSymbolAddress(&p, g_h2);    float* h2  = (float*)p;
    cudaGetSymbolAddress(&p, g_h3);    float* h3  = (float*)p;
    cudaGetSymbolAddress(&p, g_az);    float* az  = (float*)p;
    cudaGetSymbolAddress(&p, g_ah2);   float* ah2 = (float*)p;
    cudaGetSymbolAddress(&p, g_wt1hi); __nv_bfloat16* wt1hi = (__nv_bfloat16*)p;
    cudaGetSymbolAddress(&p, g_wt1lo); __nv_bfloat16* wt1lo = (__nv_bfloat16*)p;
    cudaGetSymbolAddress(&p, g_wt4hi); __nv_bfloat16* wt4hi = (__nv_bfloat16*)p;
    cudaGetSymbolAddress(&p, g_wt4lo); __nv_bfloat16* wt4lo = (__nv_bfloat16*)p;

    cudaFuncSetAttribute(mma_gemm_kernel, cudaFuncAttributeMaxDynamicSharedMemorySize, 55296);
    cudaFuncSetAttribute(ahat_mma_kernel, cudaFuncAttributeMaxDynamicSharedMemorySize, 73728);

    static cudaStream_t s2 = []() {
        cudaStream_t s; cudaStreamCreateWithFlags(&s, cudaStreamNonBlocking); return s;
    }();
    static cudaEvent_t ev0 = []() {
        cudaEvent_t e; cudaEventCreateWithFlags(&e, cudaEventDisableTiming); return e;
    }();
    static cudaEvent_t ev1 = []() {
        cudaEvent_t e; cudaEventCreateWithFlags(&e, cudaEventDisableTiming); return e;
    }();
    static cudaEvent_t ev2 = []() {
        cudaEvent_t e; cudaEventCreateWithFlags(&e, cudaEventDisableTiming); return e;
    }();
    static cudaEvent_t ev3 = []() {
        cudaEvent_t e; cudaEventCreateWithFlags(&e, cudaEventDisableTiming); return e;
    }();

    cudaStream_t s0 = 0;

    // fork; s0 CSR chain launched first (puts mma_gemm at launch slot 6 for ncu)
    cudaEventRecord(ev0, s0);

    init_kernel<<<(NNODES + 255) / 256, 256, 0, s0>>>((const int*)ei);
    count_kernel<<<(NEDGES + 255) / 256, 256, 0, s0>>>(ei);
    scan_kernel<<<1, 1024, 0, s0>>>();
    scatter_kernel<<<(NEDGES + 255) / 256, 256, 0, s0>>>(ei);

    cudaStreamWaitEvent(s2, ev0, 0);
    wprep_kernel<<<(512 * 128 + 255) / 256, 256, 0, s2>>>(W1, wt1hi, wt1lo, 512, 128);
    mma_gemm_kernel<<<dim3(2, 79), 256, 55296, s2>>>(x, wt1hi, wt1lo, nullptr, hw,
                                                     NNODES, 512, 128, 0);
    wprep_kernel<<<(128 * 512 + 255) / 256, 256, 0, s2>>>(W4, wt4hi, wt4lo, 128, 512);
    cudaEventRecord(ev1, s2);

    // join: fused agg+W2 needs CSR (s0) + t1 (s2)
    cudaStreamWaitEvent(s0, ev1, 0);
    aggw2_kernel<<<NNODES / 8, 256, 0, s0>>>(hw, W2, b1, t2);    // t2 = relu(agg(t1)+b1)@W2
    run_agg(s0, t2, b2, z, 64, 1);                               // z = relu(agg(t2)+b2)
    // fused: az = agg(z) AND h3 = relu(az@W5+b5)
    aggw5_kernel<<<NNODES / 16, dim3(16, 16), 0, s0>>>(z, W5, b5, az, h3);
    cudaEventRecord(ev2, s0);

    // critical path: ahat immediately after h3
    ahat_mma_kernel<<<3160, 256, 73728, s0>>>(h3, ahat);

    // xhat branch on s2, concurrent with ahat
    cudaStreamWaitEvent(s2, ev2, 0);
    run_gemm(s2, az, W3, b3, h2, NNODES, 128, 64, 1);            // h2 = relu(az@W3+b3)
    run_agg(s2, h2, nullptr, ah2, 128, 0);
    mma_gemm_kernel<<<dim3(8, 79), 256, 55296, s2>>>(ah2, wt4hi, wt4lo, b4, xhat,
                                                     NNODES, 128, 512, 1);
    cudaEventRecord(ev3, s2);

    // join
    cudaStreamWaitEvent(s0, ev3, 0);
}

// round 16
// speedup vs baseline: 1.0982x; 1.0982x over previous
#include <cuda_runtime.h>
#include <cuda_bf16.h>
#include <cuda_fp16.h>
#include <cstdint>

#define NNODES 10000
#define NEDGES 320000

// ---------------- device scratch (no allocations allowed) ----------------
__device__ int   g_is64;
__device__ int   g_cnt[NNODES];
__device__ int   g_fill[NNODES];
__device__ int   g_rowptr[NNODES + 1];
__device__ float g_dis[NNODES];
__device__ int   g_src[NEDGES];
__device__ float g_norm[NEDGES];
__device__ float g_hw[NNODES * 128];
__device__ float g_t2[NNODES * 64];
__device__ float g_z [NNODES * 64];
__device__ float g_h2[NNODES * 128];
__device__ float g_h3[NNODES * 64];
__device__ float g_az[NNODES * 64];
__device__ float g_ah2[NNODES * 128];
__device__ __align__(16) __nv_bfloat16 g_wt1hi[512 * 128];
__device__ __align__(16) __nv_bfloat16 g_wt1lo[512 * 128];
__device__ __align__(16) __nv_bfloat16 g_wt4hi[128 * 512];
__device__ __align__(16) __nv_bfloat16 g_wt4lo[128 * 512];

__device__ __forceinline__ int load_idx(const void* ei, int pos) {
    if (g_is64) return (int)((const long long*)ei)[pos];
    return ((const int*)ei)[pos];
}

// ---------------- fused zero + dtype detect ----------------
__global__ void init_kernel(const int* __restrict__ ei32) {
    int i = blockIdx.x * blockDim.x + threadIdx.x;
    if (i < NNODES) { g_cnt[i] = 0; g_fill[i] = 0; }
    if (i == 0) {
        int is64 = 1;
        for (int k = 0; k < 128; k++) {
            if (ei32[2 * k + 1] != 0) { is64 = 0; break; }
        }
        g_is64 = is64;
    }
}

__global__ void count_kernel(const void* __restrict__ ei) {
    int e = blockIdx.x * blockDim.x + threadIdx.x;
    if (e < NEDGES) {
        int d = load_idx(ei, NEDGES + e);
        if (d >= 0 && d < NNODES) atomicAdd(&g_cnt[d], 1);
    }
}

// warp-shuffle scan + fused dis = rsqrt(deg+1)
__global__ void scan_kernel() {
    __shared__ int warpsum[32];
    __shared__ int carry;
    int t = threadIdx.x;
    int lane = t & 31, wid = t >> 5;
    if (t == 0) { carry = 0; g_rowptr[0] = 0; }
    __syncthreads();
    for (int base = 0; base < NNODES; base += 1024) {
        int v = (base + t < NNODES) ? g_cnt[base + t] : 0;
        if (base + t < NNODES) g_dis[base + t] = rsqrtf((float)v + 1.0f);
        int x = v;
#pragma unroll
        for (int off = 1; off < 32; off <<= 1) {
            int y = __shfl_up_sync(0xffffffff, x, off);
            if (lane >= off) x += y;
        }
        if (lane == 31) warpsum[wid] = x;
        __syncthreads();
        if (wid == 0) {
            int s = warpsum[lane];
#pragma unroll
            for (int off = 1; off < 32; off <<= 1) {
                int y = __shfl_up_sync(0xffffffff, s, off);
                if (lane >= off) s += y;
            }
            warpsum[lane] = s;
        }
        __syncthreads();
        int incl = x + (wid > 0 ? warpsum[wid - 1] : 0) + carry;
        if (base + t < NNODES) g_rowptr[base + t + 1] = incl;
        __syncthreads();
        if (t == 1023) carry = incl;
        __syncthreads();
    }
}

__global__ void scatter_kernel(const void* __restrict__ ei) {
    int e = blockIdx.x * blockDim.x + threadIdx.x;
    if (e < NEDGES) {
        int srcn = load_idx(ei, e);
        int dstn = load_idx(ei, NEDGES + e);
        if (srcn < 0 || srcn >= NNODES || dstn < 0 || dstn >= NNODES) return;
        int p = g_rowptr[dstn] + atomicAdd(&g_fill[dstn], 1);
        g_src[p]  = srcn;
        g_norm[p] = g_dis[srcn] * g_dis[dstn];
    }
}

// ---------------- weight prep: bf16 split + transpose ----------------
__global__ void wprep_kernel(const float* __restrict__ W,
                             __nv_bfloat16* __restrict__ Whi,
                             __nv_bfloat16* __restrict__ Wlo, int K, int F) {
    int i = blockIdx.x * blockDim.x + threadIdx.x;
    if (i < K * F) {
        int k = i / F, f = i % F;
        float v = W[i];
        __nv_bfloat16 h = __float2bfloat16(v);
        Whi[f * K + k] = h;
        Wlo[f * K + k] = __float2bfloat16(v - __bfloat162float(h));
    }
}

// ---------------- mma.sync helpers ----------------
__device__ __forceinline__ void ldsm_x4(uint32_t* r, uint32_t addr) {
    asm volatile("ldmatrix.sync.aligned.m8n8.x4.shared.b16 {%0,%1,%2,%3}, [%4];"
                 : "=r"(r[0]), "=r"(r[1]), "=r"(r[2]), "=r"(r[3]) : "r"(addr));
}
__device__ __forceinline__ void ldsm_x2(uint32_t* r, uint32_t addr) {
    asm volatile("ldmatrix.sync.aligned.m8n8.x2.shared.b16 {%0,%1}, [%2];"
                 : "=r"(r[0]), "=r"(r[1]) : "r"(addr));
}
__device__ __forceinline__ void mma16816(float* d, const uint32_t* a, const uint32_t* b) {
    asm volatile("mma.sync.aligned.m16n8k16.row.col.f32.bf16.bf16.f32 "
                 "{%0,%1,%2,%3}, {%4,%5,%6,%7}, {%8,%9}, {%0,%1,%2,%3};"
                 : "+f"(d[0]), "+f"(d[1]), "+f"(d[2]), "+f"(d[3])
                 : "r"(a[0]), "r"(a[1]), "r"(a[2]), "r"(a[3]), "r"(b[0]), "r"(b[1]));
}
__device__ __forceinline__ void mma16816h(float* d, const uint32_t* a, const uint32_t* b) {
    asm volatile("mma.sync.aligned.m16n8k16.row.col.f32.f16.f16.f32 "
                 "{%0,%1,%2,%3}, {%4,%5,%6,%7}, {%8,%9}, {%0,%1,%2,%3};"
                 : "+f"(d[0]), "+f"(d[1]), "+f"(d[2]), "+f"(d[3])
                 : "r"(a[0]), "r"(a[1]), "r"(a[2]), "r"(a[3]), "r"(b[0]), "r"(b[1]));
}

__device__ __forceinline__ uint2 split4(float4 v, uint2& lo) {
    __nv_bfloat16 h0 = __float2bfloat16(v.x), h1 = __float2bfloat16(v.y);
    __nv_bfloat16 h2 = __float2bfloat16(v.z), h3 = __float2bfloat16(v.w);
    __nv_bfloat162 hh01 = __halves2bfloat162(h0, h1);
    __nv_bfloat162 hh23 = __halves2bfloat162(h2, h3);
    __nv_bfloat162 ll01 = __halves2bfloat162(
        __float2bfloat16(v.x - __bfloat162float(h0)),
        __float2bfloat16(v.y - __bfloat162float(h1)));
    __nv_bfloat162 ll23 = __halves2bfloat162(
        __float2bfloat16(v.z - __bfloat162float(h2)),
        __float2bfloat16(v.w - __bfloat162float(h3)));
    lo = make_uint2(*(uint32_t*)&ll01, *(uint32_t*)&ll23);
    return make_uint2(*(uint32_t*)&hh01, *(uint32_t*)&hh23);
}

// fp16 conversion of float4 (hi only)
__device__ __forceinline__ uint2 conv4h(float4 v) {
    __half2 hh01 = __halves2half2(__float2half_rn(v.x), __float2half_rn(v.y));
    __half2 hh23 = __halves2half2(__float2half_rn(v.z), __float2half_rn(v.w));
    return make_uint2(*(uint32_t*)&hh01, *(uint32_t*)&hh23);
}

// ---------------- split-bf16 TC GEMM (mma.sync), fp32 A ----------------
#define GP 72
__global__ void mma_gemm_kernel(const float* __restrict__ A,
                                const __nv_bfloat16* __restrict__ Wthi,
                                const __nv_bfloat16* __restrict__ Wtlo,
                                const float* __restrict__ bias,
                                float* __restrict__ C,
                                int M, int K, int F, int dorelu) {
    extern __shared__ __align__(16) char sm[];
    __nv_bfloat16* sAhi = (__nv_bfloat16*)sm;
    __nv_bfloat16* sAlo = sAhi + 128 * GP;
    __nv_bfloat16* sWhi = sAlo + 128 * GP;
    __nv_bfloat16* sWlo = sWhi + 64 * GP;
    int tid = threadIdx.x;
    int bm = blockIdx.y * 128, bf = blockIdx.x * 64;
    int lane = tid & 31, w = tid >> 5;
    int m0 = (w & 3) * 32, n0 = (w >> 2) * 32;
    int ra = lane & 15, ka = (lane >> 4) << 3;
    int rb = lane & 7,  kb = ((lane >> 3) & 1) << 3;
    float acc[2][4][4] = {};

    for (int k0 = 0; k0 < K; k0 += 64) {
        for (int t = tid; t < 128 * 16; t += 256) {
            int r = t >> 4, q = t & 15;
            int gr = bm + r;
            float4 v = make_float4(0.f, 0.f, 0.f, 0.f);
            if (gr < M) v = *(const float4*)(A + (size_t)gr * K + k0 + q * 4);
            uint2 lo, hi = split4(v, lo);
            *(uint2*)(sAhi + r * GP + q * 4) = hi;
            *(uint2*)(sAlo + r * GP + q * 4) = lo;
        }
        for (int t = tid; t < 64 * 8; t += 256) {
            int r = t >> 3, q = t & 7;
            uint4 vh = *(const uint4*)(Wthi + (size_t)(bf + r) * K + k0 + q * 8);
            uint4 vl = *(const uint4*)(Wtlo + (size_t)(bf + r) * K + k0 + q * 8);
            *(uint4*)(sWhi + r * GP + q * 8) = vh;
            *(uint4*)(sWlo + r * GP + q * 8) = vl;
        }
        __syncthreads();
        const __nv_bfloat16* Ats[3] = {sAhi, sAhi, sAlo};
        const __nv_bfloat16* Bts[3] = {sWhi, sWlo, sWhi};
#pragma unroll
        for (int p = 0; p < 3; p++) {
            uint32_t ab = (uint32_t)__cvta_generic_to_shared(Ats[p]);
            uint32_t bb = (uint32_t)__cvta_generic_to_shared(Bts[p]);
#pragma unroll
            for (int ks = 0; ks < 4; ks++) {
                uint32_t a[2][4];
#pragma unroll
                for (int mt = 0; mt < 2; mt++)
                    ldsm_x4(a[mt], ab + (uint32_t)(((m0 + mt * 16 + ra) * GP + ks * 16 + ka) * 2));
                uint32_t b[4][2];
#pragma unroll
                for (int nt = 0; nt < 4; nt++)
                    ldsm_x2(b[nt], bb + (uint32_t)(((n0 + nt * 8 + rb) * GP + ks * 16 + kb) * 2));
#pragma unroll
                for (int mt = 0; mt < 2; mt++)
#pragma unroll
                    for (int nt = 0; nt < 4; nt++)
                        mma16816(acc[mt][nt], a[mt], b[nt]);
            }
        }
        __syncthreads();
    }

#pragma unroll
    for (int mt = 0; mt < 2; mt++)
#pragma unroll
        for (int nt = 0; nt < 4; nt++) {
            int r = bm + m0 + mt * 16 + (lane >> 2);
            int c = bf + n0 + nt * 8 + (lane & 3) * 2;
            float v0 = acc[mt][nt][0], v1 = acc[mt][nt][1];
            float v2 = acc[mt][nt][2], v3 = acc[mt][nt][3];
            if (dorelu) {
                float bb0 = bias[c], bb1 = bias[c + 1];
                v0 = fmaxf(v0 + bb0, 0.0f); v1 = fmaxf(v1 + bb1, 0.0f);
                v2 = fmaxf(v2 + bb0, 0.0f); v3 = fmaxf(v3 + bb1, 0.0f);
            }
            if (r < M)     { C[(size_t)r * F + c] = v0;       C[(size_t)r * F + c + 1] = v1; }
            if (r + 8 < M) { C[(size_t)(r + 8) * F + c] = v2; C[(size_t)(r + 8) * F + c + 1] = v3; }
        }
}

// ---------------- SIMT GEMM (small), fused bias+relu ----------------
__global__ void gemm_kernel(const float* __restrict__ A, const float* __restrict__ B,
                            const float* __restrict__ bias, float* __restrict__ C,
                            int M, int Nn, int K, int dorelu) {
    __shared__ float As[16 * 65];
    __shared__ float Bs[16 * 64];
    int bm = blockIdx.y * 64, bn = blockIdx.x * 64;
    int tid = threadIdx.x;
    int tx = tid & 15, ty = tid >> 4;
    float acc[4][4] = {};
    for (int k0 = 0; k0 < K; k0 += 16) {
        for (int i = tid; i < 1024; i += 256) {
            int r = i >> 4, kk = i & 15;
            int gr = bm + r;
            As[kk * 65 + r] = (gr < M) ? A[(size_t)gr * K + k0 + kk] : 0.0f;
        }
        for (int i = tid; i < 1024; i += 256) {
            int kk = i >> 6, c = i & 63;
            Bs[kk * 64 + c] = B[(k0 + kk) * Nn + bn + c];
        }
        __syncthreads();
#pragma unroll
        for (int kk = 0; kk < 16; kk++) {
            float a[4], b[4];
#pragma unroll
            for (int i = 0; i < 4; i++) a[i] = As[kk * 65 + ty + 16 * i];
#pragma unroll
            for (int j = 0; j < 4; j++) b[j] = Bs[kk * 64 + tx + 16 * j];
#pragma unroll
            for (int i = 0; i < 4; i++)
#pragma unroll
                for (int j = 0; j < 4; j++) acc[i][j] += a[i] * b[j];
        }
        __syncthreads();
    }
#pragma unroll
    for (int i = 0; i < 4; i++) {
        int gr = bm + ty + 16 * i;
        if (gr < M) {
#pragma unroll
            for (int j = 0; j < 4; j++) {
                int gc = bn + tx + 16 * j;
                float v = acc[i][j];
                if (dorelu) v = fmaxf(v + bias[gc], 0.0f);
                C[(size_t)gr * Nn + gc] = v;
            }
        }
    }
}

// ---------------- fused agg(F=128)+bias+relu then @W2 (128->64) ----------------
__global__ void aggw2_kernel(const float* __restrict__ t1, const float* __restrict__ W2,
                             const float* __restrict__ b1, float* __restrict__ t2) {
    __shared__ float W2s[128 * 64];
    __shared__ float h1s[8 * 128];
    __shared__ float b1s[128];
    int tid = threadIdx.x;
    int lane = tid & 31, grp = tid >> 5;
    for (int i = tid; i < 128 * 64; i += 256) W2s[i] = W2[i];
    if (tid < 128) b1s[tid] = b1[tid];
    __syncthreads();

    int n = blockIdx.x * 8 + grp;
    const float4* h4 = (const float4*)t1;
    int f = lane;  // float4 index, F4 = 32
    float4 acc = make_float4(0.f, 0.f, 0.f, 0.f);
    int e = g_rowptr[n], end = g_rowptr[n + 1];
    for (; e + 1 < end; e += 2) {
        int s0 = g_src[e], s1 = g_src[e + 1];
        float w0 = g_norm[e], w1 = g_norm[e + 1];
        float4 v0 = h4[(size_t)s0 * 32 + f];
        float4 v1 = h4[(size_t)s1 * 32 + f];
        acc.x += v0.x * w0 + v1.x * w1;
        acc.y += v0.y * w0 + v1.y * w1;
        acc.z += v0.z * w0 + v1.z * w1;
        acc.w += v0.w * w0 + v1.w * w1;
    }
    if (e < end) {
        int s0 = g_src[e]; float w0 = g_norm[e];
        float4 v0 = h4[(size_t)s0 * 32 + f];
        acc.x += v0.x * w0; acc.y += v0.y * w0; acc.z += v0.z * w0; acc.w += v0.w * w0;
    }
    float d = g_dis[n], dd = d * d;
    float4 sv = h4[(size_t)n * 32 + f];
    float4 bb = ((const float4*)b1s)[f];
    acc.x = fmaxf(acc.x + sv.x * dd + bb.x, 0.f);
    acc.y = fmaxf(acc.y + sv.y * dd + bb.y, 0.f);
    acc.z = fmaxf(acc.z + sv.z * dd + bb.z, 0.f);
    acc.w = fmaxf(acc.w + sv.w * dd + bb.w, 0.f);
    ((float4*)h1s)[grp * 32 + f] = acc;
    __syncthreads();

    float a0 = 0.f, a1 = 0.f;
#pragma unroll 4
    for (int k = 0; k < 128; k++) {
        float a = h1s[grp * 128 + k];
        a0 += a * W2s[k * 64 + lane];
        a1 += a * W2s[k * 64 + lane + 32];
    }
    t2[(size_t)n * 64 + lane]      = a0;
    t2[(size_t)n * 64 + lane + 32] = a1;
}

// ---------------- float4 CSR aggregation (+optional bias/relu) ----------------
__global__ void agg4_kernel(const float* __restrict__ hw, const float* __restrict__ bias,
                            float* __restrict__ out, int F4, int dorelu) {
    int n = blockIdx.x * blockDim.y + threadIdx.y;
    if (n >= NNODES) return;
    int f = threadIdx.x;
    const float4* h4 = (const float4*)hw;
    int e = g_rowptr[n], end = g_rowptr[n + 1];
    float4 acc = make_float4(0.f, 0.f, 0.f, 0.f);
    for (; e + 1 < end; e += 2) {
        int s0 = g_src[e], s1 = g_src[e + 1];
        float w0 = g_norm[e], w1 = g_norm[e + 1];
        float4 v0 = h4[(size_t)s0 * F4 + f];
        float4 v1 = h4[(size_t)s1 * F4 + f];
        acc.x += v0.x * w0 + v1.x * w1;
        acc.y += v0.y * w0 + v1.y * w1;
        acc.z += v0.z * w0 + v1.z * w1;
        acc.w += v0.w * w0 + v1.w * w1;
    }
    if (e < end) {
        int s0 = g_src[e]; float w0 = g_norm[e];
        float4 v0 = h4[(size_t)s0 * F4 + f];
        acc.x += v0.x * w0; acc.y += v0.y * w0; acc.z += v0.z * w0; acc.w += v0.w * w0;
    }
    float d = g_dis[n], dd = d * d;
    float4 sv = h4[(size_t)n * F4 + f];
    acc.x += sv.x * dd; acc.y += sv.y * dd; acc.z += sv.z * dd; acc.w += sv.w * dd;
    if (bias) {
        float4 b = ((const float4*)bias)[f];
        acc.x += b.x; acc.y += b.y; acc.z += b.z; acc.w += b.w;
    }
    if (dorelu) {
        acc.x = fmaxf(acc.x, 0.f); acc.y = fmaxf(acc.y, 0.f);
        acc.z = fmaxf(acc.z, 0.f); acc.w = fmaxf(acc.w, 0.f);
    }
    ((float4*)out)[(size_t)n * F4 + f] = acc;
}

// ---------------- tensor-core a_hat = h3 @ h3^T, fp16 1-pass, triangular grid ----------------
#define AT_PITCH 72

__global__ __launch_bounds__(256) void ahat_mma_kernel(const float* __restrict__ h3,
                                                       float* __restrict__ out) {
    int bid = blockIdx.x;
    int bi = (int)(79.5f - sqrtf(79.5f * 79.5f - 2.0f * (float)bid));
    if (bi < 0) bi = 0;
    if (bi > 78) bi = 78;
#pragma unroll 4
    for (int it = 0; it < 4; it++) {
        int s  = bi * 79 - (bi * (bi - 1)) / 2;
        int s1 = (bi + 1) * 79 - ((bi + 1) * bi) / 2;
        if (bid < s) bi--;
        else if (bid >= s1) bi++;
    }
    int start = bi * 79 - (bi * (bi - 1)) / 2;
    int bj = bi + (bid - start);

    extern __shared__ __align__(16) char sm[];
    __half* Ahi = (__half*)sm;
    __half* Bhi = Ahi + 128 * AT_PITCH;

    int tid = threadIdx.x;

    for (int t = tid; t < 128 * 16; t += 256) {
        int r = t >> 4, q = t & 15;
        int ga = bi * 128 + r;
        float4 v = make_float4(0.f, 0.f, 0.f, 0.f);
        if (ga < NNODES) v = *(const float4*)(h3 + (size_t)ga * 64 + q * 4);
        *(uint2*)(Ahi + r * AT_PITCH + q * 4) = conv4h(v);
        int gb = bj * 128 + r;
        v = make_float4(0.f, 0.f, 0.f, 0.f);
        if (gb < NNODES) v = *(const float4*)(h3 + (size_t)gb * 64 + q * 4);
        *(uint2*)(Bhi + r * AT_PITCH + q * 4) = conv4h(v);
    }
    __syncthreads();

    int lane = tid & 31;
    int w = tid >> 5;
    int m0 = (w & 3) * 32;
    int n0 = (w >> 2) * 64;
    int ra = lane & 15, ka = (lane >> 4) << 3;
    int rb = lane & 7,  kb = ((lane >> 3) & 1) << 3;

    float acc[2][8][4];
#pragma unroll
    for (int mt = 0; mt < 2; mt++)
#pragma unroll
        for (int nt = 0; nt < 8; nt++)
#pragma unroll
            for (int q = 0; q < 4; q++) acc[mt][nt][q] = 0.0f;

    uint32_t abase = (uint32_t)__cvta_generic_to_shared(Ahi);
    uint32_t bbase = (uint32_t)__cvta_generic_to_shared(Bhi);
#pragma unroll
    for (int ks = 0; ks < 4; ks++) {
        uint32_t b[8][2];
#pragma unroll
        for (int nt = 0; nt < 8; nt++)
            ldsm_x2(b[nt], bbase + (uint32_t)(((n0 + nt * 8 + rb) * AT_PITCH + ks * 16 + kb) * 2));
        uint32_t a[2][4];
#pragma unroll
        for (int mt = 0; mt < 2; mt++)
            ldsm_x4(a[mt], abase + (uint32_t)(((m0 + mt * 16 + ra) * AT_PITCH + ks * 16 + ka) * 2));
#pragma unroll
        for (int mt = 0; mt < 2; mt++)
#pragma unroll
            for (int nt = 0; nt < 8; nt++)
                mma16816h(acc[mt][nt], a[mt], b[nt]);
    }
    __syncthreads();

    float* Cs = (float*)sm;  // [128][129]
#pragma unroll
    for (int mt = 0; mt < 2; mt++)
#pragma unroll
        for (int nt = 0; nt < 8; nt++) {
            int row = m0 + mt * 16 + (lane >> 2);
            int col = n0 + nt * 8 + (lane & 3) * 2;
            Cs[row * 129 + col]           = acc[mt][nt][0];
            Cs[row * 129 + col + 1]       = acc[mt][nt][1];
            Cs[(row + 8) * 129 + col]     = acc[mt][nt][2];
            Cs[(row + 8) * 129 + col + 1] = acc[mt][nt][3];
        }
    __syncthreads();

    for (int i = tid; i < 128 * 128; i += 256) {
        int r = i >> 7, c = i & 127;
        int gr = bi * 128 + r, gc = bj * 128 + c;
        if (gr < NNODES && gc < NNODES)
            out[(long long)gr * NNODES + gc] = Cs[r * 129 + c];
    }
    if (bi != bj) {
        for (int i = tid; i < 128 * 128; i += 256) {
            int r = i >> 7, c = i & 127;
            int gr = bj * 128 + r, gc = bi * 128 + c;
            if (gr < NNODES && gc < NNODES)
                out[(long long)gr * NNODES + gc] = Cs[c * 129 + r];
        }
    }
}

// ---------------- host driver ----------------
static void run_gemm(cudaStream_t s, const float* A, const float* B, const float* bias,
                     float* C, int M, int Nn, int K, int dorelu) {
    dim3 grid(Nn / 64, (M + 63) / 64);
    gemm_kernel<<<grid, 256, 0, s>>>(A, B, bias, C, M, Nn, K, dorelu);
}

static void run_agg(cudaStream_t s, const float* hw, const float* b, float* out,
                    int F, int dorelu) {
    int F4 = F / 4;
    int y = 256 / F4;
    dim3 blk(F4, y);
    dim3 grid((NNODES + y - 1) / y);
    agg4_kernel<<<grid, blk, 0, s>>>(hw, b, out, F4, dorelu);
}

extern "C" void kernel_launch(void* const* d_in, const int* in_sizes, int n_in,
                              void* d_out, int out_size) {
    const float* x  = (const float*)d_in[0];
    const void*  ei = d_in[1];
    const float* W1 = (const float*)d_in[2];  const float* b1 = (const float*)d_in[3];
    const float* W2 = (const float*)d_in[4];  const float* b2 = (const float*)d_in[5];
    const float* W3 = (const float*)d_in[6];  const float* b3 = (const float*)d_in[7];
    const float* W4 = (const float*)d_in[8];  const float* b4 = (const float*)d_in[9];
    const float* W5 = (const float*)d_in[10]; const float* b5 = (const float*)d_in[11];

    float* out  = (float*)d_out;
    float* xhat = out;
    float* ahat = out + (size_t)NNODES * 512;

    void* p;
    cudaGetSymbolAddress(&p, g_hw);    float* hw  = (float*)p;
    cudaGetSymbolAddress(&p, g_t2);    float* t2  = (float*)p;
    cudaGetSymbolAddress(&p, g_z);     float* z   = (float*)p;
    cudaGetSymbolAddress(&p, g_h2);    float* h2  = (float*)p;
    cudaGetSymbolAddress(&p, g_h3);    float* h3  = (float*)p;
    cudaGetSymbolAddress(&p, g_az);    float* az  = (float*)p;
    cudaGetSymbolAddress(&p, g_ah2);   float* ah2 = (float*)p;
    cudaGetSymbolAddress(&p, g_wt1hi); __nv_bfloat16* wt1hi = (__nv_bfloat16*)p;
    cudaGetSymbolAddress(&p, g_wt1lo); __nv_bfloat16* wt1lo = (__nv_bfloat16*)p;
    cudaGetSymbolAddress(&p, g_wt4hi); __nv_bfloat16* wt4hi = (__nv_bfloat16*)p;
    cudaGetSymbolAddress(&p, g_wt4lo); __nv_bfloat16* wt4lo = (__nv_bfloat16*)p;

    cudaFuncSetAttribute(mma_gemm_kernel, cudaFuncAttributeMaxDynamicSharedMemorySize, 55296);
    cudaFuncSetAttribute(ahat_mma_kernel, cudaFuncAttributeMaxDynamicSharedMemorySize, 73728);

    static cudaStream_t s2 = []() {
        cudaStream_t s; cudaStreamCreateWithFlags(&s, cudaStreamNonBlocking); return s;
    }();
    static cudaEvent_t ev0 = []() {
        cudaEvent_t e; cudaEventCreateWithFlags(&e, cudaEventDisableTiming); return e;
    }();
    static cudaEvent_t ev1 = []() {
        cudaEvent_t e; cudaEventCreateWithFlags(&e, cudaEventDisableTiming); return e;
    }();
    static cudaEvent_t ev2 = []() {
        cudaEvent_t e; cudaEventCreateWithFlags(&e, cudaEventDisableTiming); return e;
    }();
    static cudaEvent_t ev3 = []() {
        cudaEvent_t e; cudaEventCreateWithFlags(&e, cudaEventDisableTiming); return e;
    }();

    cudaStream_t s0 = 0;

    // fork: s2 does W1 prep + L1 TC GEMM while s0 builds the CSR.
    // ev1 recorded BEFORE wprep4 so the critical-path join doesn't wait on it.
    cudaEventRecord(ev0, s0);
    cudaStreamWaitEvent(s2, ev0, 0);

    wprep_kernel<<<(512 * 128 + 255) / 256, 256, 0, s2>>>(W1, wt1hi, wt1lo, 512, 128);
    mma_gemm_kernel<<<dim3(2, 79), 256, 55296, s2>>>(x, wt1hi, wt1lo, nullptr, hw,
                                                     NNODES, 512, 128, 0);
    cudaEventRecord(ev1, s2);
    wprep_kernel<<<(128 * 512 + 255) / 256, 256, 0, s2>>>(W4, wt4hi, wt4lo, 128, 512);

    init_kernel<<<(NNODES + 255) / 256, 256, 0, s0>>>((const int*)ei);
    count_kernel<<<(NEDGES + 255) / 256, 256, 0, s0>>>(ei);
    scan_kernel<<<1, 1024, 0, s0>>>();
    scatter_kernel<<<(NEDGES + 255) / 256, 256, 0, s0>>>(ei);

    // join: fused agg+W2 needs CSR (s0) + t1 (s2)
    cudaStreamWaitEvent(s0, ev1, 0);
    aggw2_kernel<<<NNODES / 8, 256, 0, s0>>>(hw, W2, b1, t2);    // t2 = relu(agg(t1)+b1)@W2
    run_agg(s0, t2, b2, z, 64, 1);                               // z = relu(agg(t2)+b2)
    run_agg(s0, z, nullptr, az, 64, 0);                          // az = agg(z)
    cudaEventRecord(ev2, s0);

    // critical path: h3 only, then ahat immediately
    run_gemm(s0, az, W5, b5, h3, NNODES, 64, 64, 1);             // h3 = relu(az@W5+b5)
    ahat_mma_kernel<<<3160, 256, 73728, s0>>>(h3, ahat);

    // xhat branch on s2, concurrent with ahat
    cudaStreamWaitEvent(s2, ev2, 0);
    run_gemm(s2, az, W3, b3, h2, NNODES, 128, 64, 1);            // h2 = relu(az@W3+b3)
    run_agg(s2, h2, nullptr, ah2, 128, 0);
    mma_gemm_kernel<<<dim3(8, 79), 256, 55296, s2>>>(ah2, wt4hi, wt4lo, b4, xhat,
                                                     NNODES, 128, 512, 1);
    cudaEventRecord(ev3, s2);

    // join
    cudaStreamWaitEvent(s0, ev3, 0);
}

// round 17
// speedup vs baseline: 1.1099x; 1.0106x over previous
#include <cuda_runtime.h>
#include <cuda_bf16.h>
#include <cuda_fp16.h>
#include <cstdint>

#define NNODES 10000
#define NEDGES 320000

// ---------------- device scratch (no allocations allowed) ----------------
__device__ int   g_is64;
__device__ int   g_cnt[NNODES];
__device__ int   g_fill[NNODES];
__device__ int   g_rowptr[NNODES + 1];
__device__ float g_dis[NNODES];
__device__ int   g_src[NEDGES];
__device__ float g_norm[NEDGES];
__device__ __align__(16) __half g_hwh[NNODES * 128];   // fp16 t1
__device__ float g_t2[NNODES * 64];
__device__ float g_z [NNODES * 64];
__device__ float g_h2[NNODES * 128];
__device__ float g_h3[NNODES * 64];
__device__ float g_az[NNODES * 64];
__device__ float g_ah2[NNODES * 128];
__device__ __align__(16) __nv_bfloat16 g_wt1hi[512 * 128];
__device__ __align__(16) __nv_bfloat16 g_wt1lo[512 * 128];
__device__ __align__(16) __nv_bfloat16 g_wt4hi[128 * 512];
__device__ __align__(16) __nv_bfloat16 g_wt4lo[128 * 512];

__device__ __forceinline__ int load_idx(const void* ei, int pos) {
    if (g_is64) return (int)((const long long*)ei)[pos];
    return ((const int*)ei)[pos];
}

// ---------------- fused zero + dtype detect ----------------
__global__ void init_kernel(const int* __restrict__ ei32) {
    int i = blockIdx.x * blockDim.x + threadIdx.x;
    if (i < NNODES) { g_cnt[i] = 0; g_fill[i] = 0; }
    if (i == 0) {
        int is64 = 1;
        for (int k = 0; k < 128; k++) {
            if (ei32[2 * k + 1] != 0) { is64 = 0; break; }
        }
        g_is64 = is64;
    }
}

__global__ void count_kernel(const void* __restrict__ ei) {
    int e = blockIdx.x * blockDim.x + threadIdx.x;
    if (e < NEDGES) {
        int d = load_idx(ei, NEDGES + e);
        if (d >= 0 && d < NNODES) atomicAdd(&g_cnt[d], 1);
    }
}

// warp-shuffle scan + fused dis = rsqrt(deg+1)
__global__ void scan_kernel() {
    __shared__ int warpsum[32];
    __shared__ int carry;
    int t = threadIdx.x;
    int lane = t & 31, wid = t >> 5;
    if (t == 0) { carry = 0; g_rowptr[0] = 0; }
    __syncthreads();
    for (int base = 0; base < NNODES; base += 1024) {
        int v = (base + t < NNODES) ? g_cnt[base + t] : 0;
        if (base + t < NNODES) g_dis[base + t] = rsqrtf((float)v + 1.0f);
        int x = v;
#pragma unroll
        for (int off = 1; off < 32; off <<= 1) {
            int y = __shfl_up_sync(0xffffffff, x, off);
            if (lane >= off) x += y;
        }
        if (lane == 31) warpsum[wid] = x;
        __syncthreads();
        if (wid == 0) {
            int s = warpsum[lane];
#pragma unroll
            for (int off = 1; off < 32; off <<= 1) {
                int y = __shfl_up_sync(0xffffffff, s, off);
                if (lane >= off) s += y;
            }
            warpsum[lane] = s;
        }
        __syncthreads();
        int incl = x + (wid > 0 ? warpsum[wid - 1] : 0) + carry;
        if (base + t < NNODES) g_rowptr[base + t + 1] = incl;
        __syncthreads();
        if (t == 1023) carry = incl;
        __syncthreads();
    }
}

__global__ void scatter_kernel(const void* __restrict__ ei) {
    int e = blockIdx.x * blockDim.x + threadIdx.x;
    if (e < NEDGES) {
        int srcn = load_idx(ei, e);
        int dstn = load_idx(ei, NEDGES + e);
        if (srcn < 0 || srcn >= NNODES || dstn < 0 || dstn >= NNODES) return;
        int p = g_rowptr[dstn] + atomicAdd(&g_fill[dstn], 1);
        g_src[p]  = srcn;
        g_norm[p] = g_dis[srcn] * g_dis[dstn];
    }
}

// ---------------- weight prep: bf16 split + transpose ----------------
__global__ void wprep_kernel(const float* __restrict__ W,
                             __nv_bfloat16* __restrict__ Whi,
                             __nv_bfloat16* __restrict__ Wlo, int K, int F) {
    int i = blockIdx.x * blockDim.x + threadIdx.x;
    if (i < K * F) {
        int k = i / F, f = i % F;
        float v = W[i];
        __nv_bfloat16 h = __float2bfloat16(v);
        Whi[f * K + k] = h;
        Wlo[f * K + k] = __float2bfloat16(v - __bfloat162float(h));
    }
}

// ---------------- mma.sync helpers ----------------
__device__ __forceinline__ void ldsm_x4(uint32_t* r, uint32_t addr) {
    asm volatile("ldmatrix.sync.aligned.m8n8.x4.shared.b16 {%0,%1,%2,%3}, [%4];"
                 : "=r"(r[0]), "=r"(r[1]), "=r"(r[2]), "=r"(r[3]) : "r"(addr));
}
__device__ __forceinline__ void ldsm_x2(uint32_t* r, uint32_t addr) {
    asm volatile("ldmatrix.sync.aligned.m8n8.x2.shared.b16 {%0,%1}, [%2];"
                 : "=r"(r[0]), "=r"(r[1]) : "r"(addr));
}
__device__ __forceinline__ void mma16816(float* d, const uint32_t* a, const uint32_t* b) {
    asm volatile("mma.sync.aligned.m16n8k16.row.col.f32.bf16.bf16.f32 "
                 "{%0,%1,%2,%3}, {%4,%5,%6,%7}, {%8,%9}, {%0,%1,%2,%3};"
                 : "+f"(d[0]), "+f"(d[1]), "+f"(d[2]), "+f"(d[3])
                 : "r"(a[0]), "r"(a[1]), "r"(a[2]), "r"(a[3]), "r"(b[0]), "r"(b[1]));
}
__device__ __forceinline__ void mma16816h(float* d, const uint32_t* a, const uint32_t* b) {
    asm volatile("mma.sync.aligned.m16n8k16.row.col.f32.f16.f16.f32 "
                 "{%0,%1,%2,%3}, {%4,%5,%6,%7}, {%8,%9}, {%0,%1,%2,%3};"
                 : "+f"(d[0]), "+f"(d[1]), "+f"(d[2]), "+f"(d[3])
                 : "r"(a[0]), "r"(a[1]), "r"(a[2]), "r"(a[3]), "r"(b[0]), "r"(b[1]));
}

__device__ __forceinline__ uint2 split4(float4 v, uint2& lo) {
    __nv_bfloat16 h0 = __float2bfloat16(v.x), h1 = __float2bfloat16(v.y);
    __nv_bfloat16 h2 = __float2bfloat16(v.z), h3 = __float2bfloat16(v.w);
    __nv_bfloat162 hh01 = __halves2bfloat162(h0, h1);
    __nv_bfloat162 hh23 = __halves2bfloat162(h2, h3);
    __nv_bfloat162 ll01 = __halves2bfloat162(
        __float2bfloat16(v.x - __bfloat162float(h0)),
        __float2bfloat16(v.y - __bfloat162float(h1)));
    __nv_bfloat162 ll23 = __halves2bfloat162(
        __float2bfloat16(v.z - __bfloat162float(h2)),
        __float2bfloat16(v.w - __bfloat162float(h3)));
    lo = make_uint2(*(uint32_t*)&ll01, *(uint32_t*)&ll23);
    return make_uint2(*(uint32_t*)&hh01, *(uint32_t*)&hh23);
}

// fp16 conversion of float4 (hi only)
__device__ __forceinline__ uint2 conv4h(float4 v) {
    __half2 hh01 = __halves2half2(__float2half_rn(v.x), __float2half_rn(v.y));
    __half2 hh23 = __halves2half2(__float2half_rn(v.z), __float2half_rn(v.w));
    return make_uint2(*(uint32_t*)&hh01, *(uint32_t*)&hh23);
}

// ---------------- split-bf16 TC GEMM (mma.sync), fp32 A, optional fp16 output ----------------
#define GP 72
__global__ void mma_gemm_kernel(const float* __restrict__ A,
                                const __nv_bfloat16* __restrict__ Wthi,
                                const __nv_bfloat16* __restrict__ Wtlo,
                                const float* __restrict__ bias,
                                void* __restrict__ Cv,
                                int M, int K, int F, int dorelu, int outhalf) {
    extern __shared__ __align__(16) char sm[];
    __nv_bfloat16* sAhi = (__nv_bfloat16*)sm;
    __nv_bfloat16* sAlo = sAhi + 128 * GP;
    __nv_bfloat16* sWhi = sAlo + 128 * GP;
    __nv_bfloat16* sWlo = sWhi + 64 * GP;
    int tid = threadIdx.x;
    int bm = blockIdx.y * 128, bf = blockIdx.x * 64;
    int lane = tid & 31, w = tid >> 5;
    int m0 = (w & 3) * 32, n0 = (w >> 2) * 32;
    int ra = lane & 15, ka = (lane >> 4) << 3;
    int rb = lane & 7,  kb = ((lane >> 3) & 1) << 3;
    float acc[2][4][4] = {};

    for (int k0 = 0; k0 < K; k0 += 64) {
        for (int t = tid; t < 128 * 16; t += 256) {
            int r = t >> 4, q = t & 15;
            int gr = bm + r;
            float4 v = make_float4(0.f, 0.f, 0.f, 0.f);
            if (gr < M) v = *(const float4*)(A + (size_t)gr * K + k0 + q * 4);
            uint2 lo, hi = split4(v, lo);
            *(uint2*)(sAhi + r * GP + q * 4) = hi;
            *(uint2*)(sAlo + r * GP + q * 4) = lo;
        }
        for (int t = tid; t < 64 * 8; t += 256) {
            int r = t >> 3, q = t & 7;
            uint4 vh = *(const uint4*)(Wthi + (size_t)(bf + r) * K + k0 + q * 8);
            uint4 vl = *(const uint4*)(Wtlo + (size_t)(bf + r) * K + k0 + q * 8);
            *(uint4*)(sWhi + r * GP + q * 8) = vh;
            *(uint4*)(sWlo + r * GP + q * 8) = vl;
        }
        __syncthreads();
        const __nv_bfloat16* Ats[3] = {sAhi, sAhi, sAlo};
        const __nv_bfloat16* Bts[3] = {sWhi, sWlo, sWhi};
#pragma unroll
        for (int p = 0; p < 3; p++) {
            uint32_t ab = (uint32_t)__cvta_generic_to_shared(Ats[p]);
            uint32_t bb = (uint32_t)__cvta_generic_to_shared(Bts[p]);
#pragma unroll
            for (int ks = 0; ks < 4; ks++) {
                uint32_t a[2][4];
#pragma unroll
                for (int mt = 0; mt < 2; mt++)
                    ldsm_x4(a[mt], ab + (uint32_t)(((m0 + mt * 16 + ra) * GP + ks * 16 + ka) * 2));
                uint32_t b[4][2];
#pragma unroll
                for (int nt = 0; nt < 4; nt++)
                    ldsm_x2(b[nt], bb + (uint32_t)(((n0 + nt * 8 + rb) * GP + ks * 16 + kb) * 2));
#pragma unroll
                for (int mt = 0; mt < 2; mt++)
#pragma unroll
                    for (int nt = 0; nt < 4; nt++)
                        mma16816(acc[mt][nt], a[mt], b[nt]);
            }
        }
        __syncthreads();
    }

#pragma unroll
    for (int mt = 0; mt < 2; mt++)
#pragma unroll
        for (int nt = 0; nt < 4; nt++) {
            int r = bm + m0 + mt * 16 + (lane >> 2);
            int c = bf + n0 + nt * 8 + (lane & 3) * 2;
            float v0 = acc[mt][nt][0], v1 = acc[mt][nt][1];
            float v2 = acc[mt][nt][2], v3 = acc[mt][nt][3];
            if (dorelu) {
                float bb0 = bias[c], bb1 = bias[c + 1];
                v0 = fmaxf(v0 + bb0, 0.0f); v1 = fmaxf(v1 + bb1, 0.0f);
                v2 = fmaxf(v2 + bb0, 0.0f); v3 = fmaxf(v3 + bb1, 0.0f);
            }
            if (outhalf) {
                __half* C = (__half*)Cv;
                if (r < M)     *(__half2*)(C + (size_t)r * F + c)       = __floats2half2_rn(v0, v1);
                if (r + 8 < M) *(__half2*)(C + (size_t)(r + 8) * F + c) = __floats2half2_rn(v2, v3);
            } else {
                float* C = (float*)Cv;
                if (r < M)     { C[(size_t)r * F + c] = v0;       C[(size_t)r * F + c + 1] = v1; }
                if (r + 8 < M) { C[(size_t)(r + 8) * F + c] = v2; C[(size_t)(r + 8) * F + c + 1] = v3; }
            }
        }
}

// ---------------- SIMT GEMM (small), fused bias+relu ----------------
__global__ void gemm_kernel(const float* __restrict__ A, const float* __restrict__ B,
                            const float* __restrict__ bias, float* __restrict__ C,
                            int M, int Nn, int K, int dorelu) {
    __shared__ float As[16 * 65];
    __shared__ float Bs[16 * 64];
    int bm = blockIdx.y * 64, bn = blockIdx.x * 64;
    int tid = threadIdx.x;
    int tx = tid & 15, ty = tid >> 4;
    float acc[4][4] = {};
    for (int k0 = 0; k0 < K; k0 += 16) {
        for (int i = tid; i < 1024; i += 256) {
            int r = i >> 4, kk = i & 15;
            int gr = bm + r;
            As[kk * 65 + r] = (gr < M) ? A[(size_t)gr * K + k0 + kk] : 0.0f;
        }
        for (int i = tid; i < 1024; i += 256) {
            int kk = i >> 6, c = i & 63;
            Bs[kk * 64 + c] = B[(k0 + kk) * Nn + bn + c];
        }
        __syncthreads();
#pragma unroll
        for (int kk = 0; kk < 16; kk++) {
            float a[4], b[4];
#pragma unroll
            for (int i = 0; i < 4; i++) a[i] = As[kk * 65 + ty + 16 * i];
#pragma unroll
            for (int j = 0; j < 4; j++) b[j] = Bs[kk * 64 + tx + 16 * j];
#pragma unroll
            for (int i = 0; i < 4; i++)
#pragma unroll
                for (int j = 0; j < 4; j++) acc[i][j] += a[i] * b[j];
        }
        __syncthreads();
    }
#pragma unroll
    for (int i = 0; i < 4; i++) {
        int gr = bm + ty + 16 * i;
        if (gr < M) {
#pragma unroll
            for (int j = 0; j < 4; j++) {
                int gc = bn + tx + 16 * j;
                float v = acc[i][j];
                if (dorelu) v = fmaxf(v + bias[gc], 0.0f);
                C[(size_t)gr * Nn + gc] = v;
            }
        }
    }
}

// ---------------- fused agg(F=128 fp16 input)+bias+relu then @W2 (128->64) ----------------
__global__ void aggw2_kernel(const __half* __restrict__ t1, const float* __restrict__ W2,
                             const float* __restrict__ b1, float* __restrict__ t2) {
    __shared__ float W2s[128 * 64];
    __shared__ float h1s[8 * 128];
    __shared__ float b1s[128];
    int tid = threadIdx.x;
    int lane = tid & 31, grp = tid >> 5;
    for (int i = tid; i < 128 * 64; i += 256) W2s[i] = W2[i];
    if (tid < 128) b1s[tid] = b1[tid];
    __syncthreads();

    int n = blockIdx.x * 8 + grp;
    const uint2* hh = (const uint2*)t1;   // uint2 = 4 halfs
    int f = lane;  // quad index, 32 quads = 128 features
    float4 acc = make_float4(0.f, 0.f, 0.f, 0.f);
    int e = g_rowptr[n], end = g_rowptr[n + 1];
    for (; e + 1 < end; e += 2) {
        int s0 = g_src[e], s1 = g_src[e + 1];
        float w0 = g_norm[e], w1 = g_norm[e + 1];
        uint2 u0 = hh[(size_t)s0 * 32 + f];
        uint2 u1 = hh[(size_t)s1 * 32 + f];
        float2 a01 = __half22float2(*(__half2*)&u0.x);
        float2 a23 = __half22float2(*(__half2*)&u0.y);
        float2 c01 = __half22float2(*(__half2*)&u1.x);
        float2 c23 = __half22float2(*(__half2*)&u1.y);
        acc.x += a01.x * w0 + c01.x * w1;
        acc.y += a01.y * w0 + c01.y * w1;
        acc.z += a23.x * w0 + c23.x * w1;
        acc.w += a23.y * w0 + c23.y * w1;
    }
    if (e < end) {
        int s0 = g_src[e]; float w0 = g_norm[e];
        uint2 u0 = hh[(size_t)s0 * 32 + f];
        float2 a01 = __half22float2(*(__half2*)&u0.x);
        float2 a23 = __half22float2(*(__half2*)&u0.y);
        acc.x += a01.x * w0; acc.y += a01.y * w0; acc.z += a23.x * w0; acc.w += a23.y * w0;
    }
    float d = g_dis[n], dd = d * d;
    uint2 us = hh[(size_t)n * 32 + f];
    float2 s01 = __half22float2(*(__half2*)&us.x);
    float2 s23 = __half22float2(*(__half2*)&us.y);
    float4 bb = ((const float4*)b1s)[f];
    acc.x = fmaxf(acc.x + s01.x * dd + bb.x, 0.f);
    acc.y = fmaxf(acc.y + s01.y * dd + bb.y, 0.f);
    acc.z = fmaxf(acc.z + s23.x * dd + bb.z, 0.f);
    acc.w = fmaxf(acc.w + s23.y * dd + bb.w, 0.f);
    ((float4*)h1s)[grp * 32 + f] = acc;
    __syncthreads();

    float a0 = 0.f, a1 = 0.f;
#pragma unroll 4
    for (int k = 0; k < 128; k++) {
        float a = h1s[grp * 128 + k];
        a0 += a * W2s[k * 64 + lane];
        a1 += a * W2s[k * 64 + lane + 32];
    }
    t2[(size_t)n * 64 + lane]      = a0;
    t2[(size_t)n * 64 + lane + 32] = a1;
}

// ---------------- float4 CSR aggregation (+optional bias/relu) ----------------
__global__ void agg4_kernel(const float* __restrict__ hw, const float* __restrict__ bias,
                            float* __restrict__ out, int F4, int dorelu) {
    int n = blockIdx.x * blockDim.y + threadIdx.y;
    if (n >= NNODES) return;
    int f = threadIdx.x;
    const float4* h4 = (const float4*)hw;
    int e = g_rowptr[n], end = g_rowptr[n + 1];
    float4 acc = make_float4(0.f, 0.f, 0.f, 0.f);
    for (; e + 1 < end; e += 2) {
        int s0 = g_src[e], s1 = g_src[e + 1];
        float w0 = g_norm[e], w1 = g_norm[e + 1];
        float4 v0 = h4[(size_t)s0 * F4 + f];
        float4 v1 = h4[(size_t)s1 * F4 + f];
        acc.x += v0.x * w0 + v1.x * w1;
        acc.y += v0.y * w0 + v1.y * w1;
        acc.z += v0.z * w0 + v1.z * w1;
        acc.w += v0.w * w0 + v1.w * w1;
    }
    if (e < end) {
        int s0 = g_src[e]; float w0 = g_norm[e];
        float4 v0 = h4[(size_t)s0 * F4 + f];
        acc.x += v0.x * w0; acc.y += v0.y * w0; acc.z += v0.z * w0; acc.w += v0.w * w0;
    }
    float d = g_dis[n], dd = d * d;
    float4 sv = h4[(size_t)n * F4 + f];
    acc.x += sv.x * dd; acc.y += sv.y * dd; acc.z += sv.z * dd; acc.w += sv.w * dd;
    if (bias) {
        float4 b = ((const float4*)bias)[f];
        acc.x += b.x; acc.y += b.y; acc.z += b.z; acc.w += b.w;
    }
    if (dorelu) {
        acc.x = fmaxf(acc.x, 0.f); acc.y = fmaxf(acc.y, 0.f);
        acc.z = fmaxf(acc.z, 0.f); acc.w = fmaxf(acc.w, 0.f);
    }
    ((float4*)out)[(size_t)n * F4 + f] = acc;
}

// ---------------- tensor-core a_hat = h3 @ h3^T, fp16 1-pass, triangular grid ----------------
#define AT_PITCH 72

__global__ __launch_bounds__(256) void ahat_mma_kernel(const float* __restrict__ h3,
                                                       float* __restrict__ out) {
    int bid = blockIdx.x;
    int bi = (int)(79.5f - sqrtf(79.5f * 79.5f - 2.0f * (float)bid));
    if (bi < 0) bi = 0;
    if (bi > 78) bi = 78;
#pragma unroll 4
    for (int it = 0; it < 4; it++) {
        int s  = bi * 79 - (bi * (bi - 1)) / 2;
        int s1 = (bi + 1) * 79 - ((bi + 1) * bi) / 2;
        if (bid < s) bi--;
        else if (bid >= s1) bi++;
    }
    int start = bi * 79 - (bi * (bi - 1)) / 2;
    int bj = bi + (bid - start);

    extern __shared__ __align__(16) char sm[];
    __half* Ahi = (__half*)sm;
    __half* Bhi = Ahi + 128 * AT_PITCH;

    int tid = threadIdx.x;

    for (int t = tid; t < 128 * 16; t += 256) {
        int r = t >> 4, q = t & 15;
        int ga = bi * 128 + r;
        float4 v = make_float4(0.f, 0.f, 0.f, 0.f);
        if (ga < NNODES) v = *(const float4*)(h3 + (size_t)ga * 64 + q * 4);
        *(uint2*)(Ahi + r * AT_PITCH + q * 4) = conv4h(v);
        int gb = bj * 128 + r;
        v = make_float4(0.f, 0.f, 0.f, 0.f);
        if (gb < NNODES) v = *(const float4*)(h3 + (size_t)gb * 64 + q * 4);
        *(uint2*)(Bhi + r * AT_PITCH + q * 4) = conv4h(v);
    }
    __syncthreads();

    int lane = tid & 31;
    int w = tid >> 5;
    int m0 = (w & 3) * 32;
    int n0 = (w >> 2) * 64;
    int ra = lane & 15, ka = (lane >> 4) << 3;
    int rb = lane & 7,  kb = ((lane >> 3) & 1) << 3;

    float acc[2][8][4];
#pragma unroll
    for (int mt = 0; mt < 2; mt++)
#pragma unroll
        for (int nt = 0; nt < 8; nt++)
#pragma unroll
            for (int q = 0; q < 4; q++) acc[mt][nt][q] = 0.0f;

    uint32_t abase = (uint32_t)__cvta_generic_to_shared(Ahi);
    uint32_t bbase = (uint32_t)__cvta_generic_to_shared(Bhi);
#pragma unroll
    for (int ks = 0; ks < 4; ks++) {
        uint32_t b[8][2];
#pragma unroll
        for (int nt = 0; nt < 8; nt++)
            ldsm_x2(b[nt], bbase + (uint32_t)(((n0 + nt * 8 + rb) * AT_PITCH + ks * 16 + kb) * 2));
        uint32_t a[2][4];
#pragma unroll
        for (int mt = 0; mt < 2; mt++)
            ldsm_x4(a[mt], abase + (uint32_t)(((m0 + mt * 16 + ra) * AT_PITCH + ks * 16 + ka) * 2));
#pragma unroll
        for (int mt = 0; mt < 2; mt++)
#pragma unroll
            for (int nt = 0; nt < 8; nt++)
                mma16816h(acc[mt][nt], a[mt], b[nt]);
    }
    __syncthreads();

    float* Cs = (float*)sm;  // [128][129]
#pragma unroll
    for (int mt = 0; mt < 2; mt++)
#pragma unroll
        for (int nt = 0; nt < 8; nt++) {
            int row = m0 + mt * 16 + (lane >> 2);
            int col = n0 + nt * 8 + (lane & 3) * 2;
            Cs[row * 129 + col]           = acc[mt][nt][0];
            Cs[row * 129 + col + 1]       = acc[mt][nt][1];
            Cs[(row + 8) * 129 + col]     = acc[mt][nt][2];
            Cs[(row + 8) * 129 + col + 1] = acc[mt][nt][3];
        }
    __syncthreads();

    for (int i = tid; i < 128 * 128; i += 256) {
        int r = i >> 7, c = i & 127;
        int gr = bi * 128 + r, gc = bj * 128 + c;
        if (gr < NNODES && gc < NNODES)
            out[(long long)gr * NNODES + gc] = Cs[r * 129 + c];
    }
    if (bi != bj) {
        for (int i = tid; i < 128 * 128; i += 256) {
            int r = i >> 7, c = i & 127;
            int gr = bj * 128 + r, gc = bi * 128 + c;
            if (gr < NNODES && gc < NNODES)
                out[(long long)gr * NNODES + gc] = Cs[c * 129 + r];
        }
    }
}

// ---------------- host driver ----------------
static void run_gemm(cudaStream_t s, const float* A, const float* B, const float* bias,
                     float* C, int M, int Nn, int K, int dorelu) {
    dim3 grid(Nn / 64, (M + 63) / 64);
    gemm_kernel<<<grid, 256, 0, s>>>(A, B, bias, C, M, Nn, K, dorelu);
}

static void run_agg(cudaStream_t s, const float* hw, const float* b, float* out,
                    int F, int dorelu) {
    int F4 = F / 4;
    int y = 256 / F4;
    dim3 blk(F4, y);
    dim3 grid((NNODES + y - 1) / y);
    agg4_kernel<<<grid, blk, 0, s>>>(hw, b, out, F4, dorelu);
}

extern "C" void kernel_launch(void* const* d_in, const int* in_sizes, int n_in,
                              void* d_out, int out_size) {
    const float* x  = (const float*)d_in[0];
    const void*  ei = d_in[1];
    const float* W1 = (const float*)d_in[2];  const float* b1 = (const float*)d_in[3];
    const float* W2 = (const float*)d_in[4];  const float* b2 = (const float*)d_in[5];
    const float* W3 = (const float*)d_in[6];  const float* b3 = (const float*)d_in[7];
    const float* W4 = (const float*)d_in[8];  const float* b4 = (const float*)d_in[9];
    const float* W5 = (const float*)d_in[10]; const float* b5 = (const float*)d_in[11];

    float* out  = (float*)d_out;
    float* xhat = out;
    float* ahat = out + (size_t)NNODES * 512;

    void* p;
    cudaGetSymbolAddress(&p, g_hwh);   __half* hwh = (__half*)p;
    cudaGetSymbolAddress(&p, g_t2);    float* t2  = (float*)p;
    cudaGetSymbolAddress(&p, g_z);     float* z   = (float*)p;
    cudaGetSymbolAddress(&p, g_h2);    float* h2  = (float*)p;
    cudaGetSymbolAddress(&p, g_h3);    float* h3  = (float*)p;
    cudaGetSymbolAddress(&p, g_az);    float* az  = (float*)p;
    cudaGetSymbolAddress(&p, g_ah2);   float* ah2 = (float*)p;
    cudaGetSymbolAddress(&p, g_wt1hi); __nv_bfloat16* wt1hi = (__nv_bfloat16*)p;
    cudaGetSymbolAddress(&p, g_wt1lo); __nv_bfloat16* wt1lo = (__nv_bfloat16*)p;
    cudaGetSymbolAddress(&p, g_wt4hi); __nv_bfloat16* wt4hi = (__nv_bfloat16*)p;
    cudaGetSymbolAddress(&p, g_wt4lo); __nv_bfloat16* wt4lo = (__nv_bfloat16*)p;

    cudaFuncSetAttribute(mma_gemm_kernel, cudaFuncAttributeMaxDynamicSharedMemorySize, 55296);
    cudaFuncSetAttribute(ahat_mma_kernel, cudaFuncAttributeMaxDynamicSharedMemorySize, 73728);

    static cudaStream_t s2 = []() {
        cudaStream_t s; cudaStreamCreateWithFlags(&s, cudaStreamNonBlocking); return s;
    }();
    static cudaEvent_t ev0 = []() {
        cudaEvent_t e; cudaEventCreateWithFlags(&e, cudaEventDisableTiming); return e;
    }();
    static cudaEvent_t ev1 = []() {
        cudaEvent_t e; cudaEventCreateWithFlags(&e, cudaEventDisableTiming); return e;
    }();
    static cudaEvent_t ev2 = []() {
        cudaEvent_t e; cudaEventCreateWithFlags(&e, cudaEventDisableTiming); return e;
    }();
    static cudaEvent_t ev3 = []() {
        cudaEvent_t e; cudaEventCreateWithFlags(&e, cudaEventDisableTiming); return e;
    }();

    cudaStream_t s0 = 0;

    // fork: s2 does W1 prep + L1 TC GEMM (fp16 out) while s0 builds the CSR.
    cudaEventRecord(ev0, s0);
    cudaStreamWaitEvent(s2, ev0, 0);

    wprep_kernel<<<(512 * 128 + 255) / 256, 256, 0, s2>>>(W1, wt1hi, wt1lo, 512, 128);
    mma_gemm_kernel<<<dim3(2, 79), 256, 55296, s2>>>(x, wt1hi, wt1lo, nullptr, hwh,
                                                     NNODES, 512, 128, 0, 1);
    cudaEventRecord(ev1, s2);
    wprep_kernel<<<(128 * 512 + 255) / 256, 256, 0, s2>>>(W4, wt4hi, wt4lo, 128, 512);

    init_kernel<<<(NNODES + 255) / 256, 256, 0, s0>>>((const int*)ei);
    count_kernel<<<(NEDGES + 255) / 256, 256, 0, s0>>>(ei);
    scan_kernel<<<1, 1024, 0, s0>>>();
    scatter_kernel<<<(NEDGES + 255) / 256, 256, 0, s0>>>(ei);

    // join: fused agg+W2 needs CSR (s0) + t1 (s2)
    cudaStreamWaitEvent(s0, ev1, 0);
    aggw2_kernel<<<NNODES / 8, 256, 0, s0>>>(hwh, W2, b1, t2);   // t2 = relu(agg(t1)+b1)@W2
    run_agg(s0, t2, b2, z, 64, 1);                               // z = relu(agg(t2)+b2)
    run_agg(s0, z, nullptr, az, 64, 0);                          // az = agg(z)
    cudaEventRecord(ev2, s0);

    // critical path: h3 only, then ahat immediately
    run_gemm(s0, az, W5, b5, h3, NNODES, 64, 64, 1);             // h3 = relu(az@W5+b5)
    ahat_mma_kernel<<<3160, 256, 73728, s0>>>(h3, ahat);

    // xhat branch on s2, concurrent with ahat
    cudaStreamWaitEvent(s2, ev2, 0);
    run_gemm(s2, az, W3, b3, h2, NNODES, 128, 64, 1);            // h2 = relu(az@W3+b3)
    run_agg(s2, h2, nullptr, ah2, 128, 0);
    mma_gemm_kernel<<<dim3(8, 79), 256, 55296, s2>>>(ah2, wt4hi, wt4lo, b4, xhat,
                                                     NNODES, 128, 512, 1, 0);
    cudaEventRecord(ev3, s2);

    // join
    cudaStreamWaitEvent(s0, ev3, 0);
}